// round 3
// baseline (speedup 1.0000x reference)
#include <cuda_runtime.h>
#include <cstddef>

#define NN   100000
#define EE   1600000
#define IND  128
#define HH   64
#define RR   4
#define GG   128
#define OUTD 10
#define MC   960   // concatenated dense output width: 64 skip + 128 Fskip + 4*64 hrel + 4*128 film
#define RN   (RR * NN)          // 400000 (r,dst) bins
#define SCAN_BS 1024
#define SCAN_NB ((RN + SCAN_BS - 1) / SCAN_BS)   // 391

// Column offsets inside C[N, 960]
#define OFF_SKIPW 0
#define OFF_SBETA 64
#define OFF_SGAMM 128
#define OFF_HREL  192   // + r*64
#define OFF_FILM  448   // + r*128  (beta 0..63 | gamma 64..127)

// ---------------------------------------------------------------------------
// Scratch (static __device__ globals; no allocation anywhere)
// ---------------------------------------------------------------------------
__device__ float g_h0  [(size_t)NN * HH];         // encoder output / layer-1 input
__device__ float g_h1  [(size_t)NN * HH];         // post layer0 + BN + ReLU
__device__ float g_C   [(size_t)NN * MC];         // fused dense output per layer
__device__ float g_Wcat[2][(size_t)HH * MC];      // packed weights per layer
__device__ float g_sums[(size_t)RR * NN * HH];    // per-(r,dst) message MEANS
__device__ float g_pool[GG * HH];                 // global_add_pool
// CSR build (shared by both layers)
__device__ int   g_icnt  [RN];                    // per-bin edge counts
__device__ int   g_off   [RN];                    // exclusive prefix (CSR offsets)
__device__ int   g_cursor[RN];                    // scatter cursors
__device__ int   g_bsum  [SCAN_NB + 1];           // block sums for scan
__device__ int   g_ssrc  [EE];                    // src ids sorted by (r,dst) bin

// ---------------------------------------------------------------------------
// Helpers
// ---------------------------------------------------------------------------
__device__ __forceinline__ void redAddF4(float4* p, float4 v) {
    asm volatile("red.global.add.v4.f32 [%0], {%1, %2, %3, %4};"
                 :: "l"(p), "f"(v.x), "f"(v.y), "f"(v.z), "f"(v.w) : "memory");
}
__device__ __forceinline__ unsigned long long packf2(float x, float y) {
    unsigned long long u;
    asm("mov.b64 %0, {%1, %2};" : "=l"(u) : "f"(x), "f"(y));
    return u;
}
__device__ __forceinline__ float2 unpackf2(unsigned long long u) {
    float2 f;
    asm("mov.b64 {%0, %1}, %2;" : "=f"(f.x), "=f"(f.y) : "l"(u));
    return f;
}
__device__ __forceinline__ unsigned long long fma2(unsigned long long a,
                                                   unsigned long long b,
                                                   unsigned long long c) {
    unsigned long long d;
    asm("fma.rn.f32x2 %0, %1, %2, %3;" : "=l"(d) : "l"(a), "l"(b), "l"(c));
    return d;
}

// ---------------------------------------------------------------------------
// Weight pack: Wcat[k][0:64)=W_skip[k], [64:192)=F_skip[k],
//              [192+r*64+m]=W_rel[r][k][m], [448+r*128+m]=F_rel[r][k][m]
// ---------------------------------------------------------------------------
__global__ void pack_weights_kernel(const float* __restrict__ Ws,
                                    const float* __restrict__ Fs,
                                    const float* __restrict__ Wr,
                                    const float* __restrict__ Fr,
                                    float* __restrict__ Wcat)
{
    int idx = blockIdx.x * blockDim.x + threadIdx.x;
    if (idx >= HH * MC) return;
    int k = idx / MC, m = idx % MC;
    float v;
    if (m < 64)       v = Ws[k * 64 + m];
    else if (m < 192) v = Fs[k * 128 + (m - 64)];
    else if (m < 448) { int r = (m - 192) >> 6; int c = (m - 192) & 63;
                        v = Wr[((long)r * 64 + k) * 64 + c]; }
    else              { int r = (m - 448) >> 7; int c = (m - 448) & 127;
                        v = Fr[((long)r * 64 + k) * 128 + c]; }
    Wcat[idx] = v;
}

// ---------------------------------------------------------------------------
// CSR build: histogram -> scan -> scatter
// ---------------------------------------------------------------------------
__global__ void hist_kernel(const int* __restrict__ dst,
                            const int* __restrict__ et,
                            int* __restrict__ icnt)
{
    int e = blockIdx.x * blockDim.x + threadIdx.x;
    if (e >= EE) return;
    atomicAdd(&icnt[et[e] * NN + dst[e]], 1);
}

// Per-block exclusive scan + block totals (Hillis-Steele in shared).
__global__ __launch_bounds__(SCAN_BS)
void scan1_kernel(const int* __restrict__ in, int* __restrict__ out,
                  int* __restrict__ bsum, int n)
{
    __shared__ int sh[SCAN_BS];
    int tid = threadIdx.x;
    int i = blockIdx.x * SCAN_BS + tid;
    int v = (i < n) ? in[i] : 0;
    int x = v;
    sh[tid] = x;
    __syncthreads();
    for (int off = 1; off < SCAN_BS; off <<= 1) {
        int t = (tid >= off) ? sh[tid - off] : 0;
        __syncthreads();
        x += t;
        sh[tid] = x;
        __syncthreads();
    }
    if (i < n) out[i] = x - v;                 // exclusive (block-local)
    if (tid == SCAN_BS - 1) bsum[blockIdx.x] = x;
}

// Exclusive scan of block sums (single block; nb <= SCAN_BS).
__global__ __launch_bounds__(SCAN_BS)
void scan2_kernel(int* __restrict__ bsum, int nb)
{
    __shared__ int sh[SCAN_BS];
    int tid = threadIdx.x;
    int v = (tid < nb) ? bsum[tid] : 0;
    int x = v;
    sh[tid] = x;
    __syncthreads();
    for (int off = 1; off < SCAN_BS; off <<= 1) {
        int t = (tid >= off) ? sh[tid - off] : 0;
        __syncthreads();
        x += t;
        sh[tid] = x;
        __syncthreads();
    }
    if (tid < nb) bsum[tid] = x - v;           // exclusive
}

__global__ void scan3_kernel(int* __restrict__ out, const int* __restrict__ bsum, int n)
{
    int i = blockIdx.x * blockDim.x + threadIdx.x;
    if (i < n) out[i] += bsum[blockIdx.x * blockDim.x / SCAN_BS + (threadIdx.x + blockIdx.x * blockDim.x) / SCAN_BS - (blockIdx.x * blockDim.x + threadIdx.x) / SCAN_BS + (i / SCAN_BS)]; // simplified below
}

// (replacement, simple and correct)
__global__ void scan3b_kernel(int* __restrict__ out, const int* __restrict__ bsum, int n)
{
    int i = blockIdx.x * blockDim.x + threadIdx.x;
    if (i < n) out[i] += bsum[i / SCAN_BS];
}

__global__ void scatter_kernel(const int* __restrict__ src,
                               const int* __restrict__ dst,
                               const int* __restrict__ et,
                               const int* __restrict__ off,
                               int* __restrict__ cursor,
                               int* __restrict__ ssrc)
{
    int e = blockIdx.x * blockDim.x + threadIdx.x;
    if (e >= EE) return;
    int bin = et[e] * NN + dst[e];
    int pos = atomicAdd(&cursor[bin], 1);
    ssrc[off[bin] + pos] = src[e];
}

// ---------------------------------------------------------------------------
// Tiled fp32 GEMM with packed f32x2 FMA.
// C[N,M] = X[N,K] @ W[K,M] (+ bias). K % 32 == 0, M % 64 == 0.
// Block tile 128(N) x 64(M), 256 threads, per-thread 8x4 (rows paired in f32x2).
// ---------------------------------------------------------------------------
#define GT_N 128
#define GT_M 64
#define GT_K 32

__global__ __launch_bounds__(256)
void gemm_kernel(const float* __restrict__ X,
                 const float* __restrict__ W,
                 const float* __restrict__ bias,
                 float* __restrict__ C,
                 int N, int K, int M)
{
    __shared__ float Xs[GT_K][GT_N + 2];   // transposed: Xs[k][row]
    __shared__ float Ws[GT_K][GT_M];

    const int n0 = blockIdx.y * GT_N;
    const int m0 = blockIdx.x * GT_M;
    const int t  = threadIdx.x;
    const int tx = t & 15;     // col group: 4 cols
    const int ty = t >> 4;     // row group: 8 rows (4 pairs)

    unsigned long long acc[4][4];
    #pragma unroll
    for (int p = 0; p < 4; p++)
        #pragma unroll
        for (int c = 0; c < 4; c++) acc[p][c] = 0ULL;

    for (int k0 = 0; k0 < K; k0 += GT_K) {
        #pragma unroll
        for (int idx = t; idx < GT_N * GT_K; idx += 256) {
            int r = idx >> 5, c = idx & 31;
            int n = n0 + r;
            Xs[c][r] = (n < N) ? X[(long)n * K + k0 + c] : 0.f;
        }
        #pragma unroll
        for (int idx = t; idx < GT_K * GT_M; idx += 256) {
            int r = idx >> 6, c = idx & 63;
            Ws[r][c] = W[(long)(k0 + r) * M + m0 + c];
        }
        __syncthreads();

        #pragma unroll
        for (int kk = 0; kk < GT_K; kk++) {
            unsigned long long a0 = *(const unsigned long long*)&Xs[kk][ty * 8 + 0];
            unsigned long long a1 = *(const unsigned long long*)&Xs[kk][ty * 8 + 2];
            unsigned long long a2 = *(const unsigned long long*)&Xs[kk][ty * 8 + 4];
            unsigned long long a3 = *(const unsigned long long*)&Xs[kk][ty * 8 + 6];
            float4 b = *(const float4*)&Ws[kk][tx * 4];
            unsigned long long b0 = packf2(b.x, b.x);
            unsigned long long b1 = packf2(b.y, b.y);
            unsigned long long b2 = packf2(b.z, b.z);
            unsigned long long b3 = packf2(b.w, b.w);
            acc[0][0] = fma2(a0, b0, acc[0][0]);
            acc[0][1] = fma2(a0, b1, acc[0][1]);
            acc[0][2] = fma2(a0, b2, acc[0][2]);
            acc[0][3] = fma2(a0, b3, acc[0][3]);
            acc[1][0] = fma2(a1, b0, acc[1][0]);
            acc[1][1] = fma2(a1, b1, acc[1][1]);
            acc[1][2] = fma2(a1, b2, acc[1][2]);
            acc[1][3] = fma2(a1, b3, acc[1][3]);
            acc[2][0] = fma2(a2, b0, acc[2][0]);
            acc[2][1] = fma2(a2, b1, acc[2][1]);
            acc[2][2] = fma2(a2, b2, acc[2][2]);
            acc[2][3] = fma2(a2, b3, acc[2][3]);
            acc[3][0] = fma2(a3, b0, acc[3][0]);
            acc[3][1] = fma2(a3, b1, acc[3][1]);
            acc[3][2] = fma2(a3, b2, acc[3][2]);
            acc[3][3] = fma2(a3, b3, acc[3][3]);
        }
        __syncthreads();
    }

    float4 bv = make_float4(0.f, 0.f, 0.f, 0.f);
    if (bias) {
        bv.x = bias[m0 + tx * 4 + 0];
        bv.y = bias[m0 + tx * 4 + 1];
        bv.z = bias[m0 + tx * 4 + 2];
        bv.w = bias[m0 + tx * 4 + 3];
    }
    #pragma unroll
    for (int p = 0; p < 4; p++) {
        int n = n0 + ty * 8 + 2 * p;
        float2 c0 = unpackf2(acc[p][0]);
        float2 c1 = unpackf2(acc[p][1]);
        float2 c2 = unpackf2(acc[p][2]);
        float2 c3 = unpackf2(acc[p][3]);
        if (n < N) {
            float4 v = make_float4(c0.x + bv.x, c1.x + bv.y, c2.x + bv.z, c3.x + bv.w);
            *(float4*)&C[(long)n * M + m0 + tx * 4] = v;
        }
        if (n + 1 < N) {
            float4 v = make_float4(c0.y + bv.x, c1.y + bv.y, c2.y + bv.z, c3.y + bv.w);
            *(float4*)&C[(long)(n + 1) * M + m0 + tx * 4] = v;
        }
    }
}

// ---------------------------------------------------------------------------
// Gather: one half-warp (16 lanes, float4) per (r,dst) bin.
// sums[r,dst] = mean_i relu(gamma[r,dst] * h_rel[r, src_i] + beta[r,dst])
// gamma/beta loaded ONCE per bin; no atomics; writes zeros for empty bins.
// ---------------------------------------------------------------------------
__global__ __launch_bounds__(256)
void gather_kernel(const int* __restrict__ ssrc,
                   const int* __restrict__ off,
                   const int* __restrict__ icnt,
                   const float* __restrict__ C,
                   float* __restrict__ sums)
{
    int bin  = (blockIdx.x * blockDim.x + threadIdx.x) >> 4;
    int lane = threadIdx.x & 15;
    if (bin >= RN) return;
    int r = bin / NN, d = bin - r * NN;

    float4 acc = make_float4(0.f, 0.f, 0.f, 0.f);
    int c = icnt[bin];
    if (c > 0) {
        const float4* f4 = (const float4*)(C + (long)d * MC + OFF_FILM + r * 128);
        float4 be = f4[lane];
        float4 ga = f4[16 + lane];
        int base = off[bin];
        for (int i = 0; i < c; i++) {
            int s = ssrc[base + i];
            float4 h = *(const float4*)(C + (long)s * MC + OFF_HREL + r * 64 + lane * 4);
            acc.x += fmaxf(ga.x * h.x + be.x, 0.f);
            acc.y += fmaxf(ga.y * h.y + be.y, 0.f);
            acc.z += fmaxf(ga.z * h.z + be.z, 0.f);
            acc.w += fmaxf(ga.w * h.w + be.w, 0.f);
        }
        float inv = 1.0f / (float)c;
        acc.x *= inv; acc.y *= inv; acc.z *= inv; acc.w *= inv;
    }
    *(float4*)(sums + (long)bin * HH + lane * 4) = acc;
}

// ---------------------------------------------------------------------------
// Finalize (fused skip): node = relu(gamma_s*w + beta_s) + sum_r mean[r][node]
//   mode 0: apply BN(eval)+ReLU, write out_nodes (layer 0)
//   mode 1: red-add into pool[batch[node]]        (layer 1)
// ---------------------------------------------------------------------------
__global__ void finalize_kernel(const float* __restrict__ C,
                                const float* __restrict__ sums,
                                const float* __restrict__ bn_g,
                                const float* __restrict__ bn_b,
                                float* __restrict__ out_nodes,
                                const int* __restrict__ batch,
                                float* __restrict__ pool,
                                int mode)
{
    long idx = (long)blockIdx.x * blockDim.x + threadIdx.x;
    if (idx >= (long)NN * 16) return;
    int n = (int)(idx >> 4);
    int q = (int)(idx & 15);

    const float* row = C + (long)n * MC;
    float4 w  = *(const float4*)(row + OFF_SKIPW + q * 4);
    float4 be = *(const float4*)(row + OFF_SBETA + q * 4);
    float4 ga = *(const float4*)(row + OFF_SGAMM + q * 4);
    float4 v;
    v.x = fmaxf(ga.x * w.x + be.x, 0.f);
    v.y = fmaxf(ga.y * w.y + be.y, 0.f);
    v.z = fmaxf(ga.z * w.z + be.z, 0.f);
    v.w = fmaxf(ga.w * w.w + be.w, 0.f);

    #pragma unroll
    for (int r = 0; r < RR; r++) {
        float4 s = *(const float4*)(sums + ((long)r * NN + n) * HH + q * 4);
        v.x += s.x; v.y += s.y; v.z += s.z; v.w += s.w;
    }
    if (mode == 0) {
        int cb = q * 4;
        float sc = rsqrtf(1.0f + 1e-5f);
        v.x = fmaxf(v.x * (bn_g[cb + 0] * sc) + bn_b[cb + 0], 0.f);
        v.y = fmaxf(v.y * (bn_g[cb + 1] * sc) + bn_b[cb + 1], 0.f);
        v.z = fmaxf(v.z * (bn_g[cb + 2] * sc) + bn_b[cb + 2], 0.f);
        v.w = fmaxf(v.w * (bn_g[cb + 3] * sc) + bn_b[cb + 3], 0.f);
        *(float4*)(out_nodes + (long)n * HH + q * 4) = v;
    } else {
        int g = batch[n];
        redAddF4((float4*)(pool + (long)g * HH + q * 4), v);
    }
}

// ---------------------------------------------------------------------------
// Head: out = relu(pool @ lin_W + lin_b) @ clf_W + clf_b. One block, 128 thr.
// ---------------------------------------------------------------------------
__global__ __launch_bounds__(128)
void head_kernel(const float* __restrict__ pool,
                 const float* __restrict__ lin_W, const float* __restrict__ lin_b,
                 const float* __restrict__ clf_W, const float* __restrict__ clf_b,
                 float* __restrict__ out)
{
    __shared__ float sW[HH * HH];
    __shared__ float sC[HH * OUTD];
    __shared__ float sb[HH];
    __shared__ float scb[OUTD];
    int t = threadIdx.x;
    for (int i = t; i < HH * HH;   i += 128) sW[i] = lin_W[i];
    for (int i = t; i < HH * OUTD; i += 128) sC[i] = clf_W[i];
    if (t < HH)   sb[t]  = lin_b[t];
    if (t < OUTD) scb[t] = clf_b[t];
    __syncthreads();

    float p[HH];
    #pragma unroll
    for (int i = 0; i < HH; i++) p[i] = pool[t * HH + i];

    float hid[HH];
    #pragma unroll
    for (int j = 0; j < HH; j++) {
        float a = sb[j];
        #pragma unroll
        for (int i = 0; i < HH; i++) a += p[i] * sW[i * HH + j];
        hid[j] = fmaxf(a, 0.f);
    }
    #pragma unroll
    for (int o = 0; o < OUTD; o++) {
        float a = scb[o];
        #pragma unroll
        for (int j = 0; j < HH; j++) a += hid[j] * sC[j * OUTD + o];
        out[t * OUTD + o] = a;
    }
}

// ---------------------------------------------------------------------------
// Host orchestration
// ---------------------------------------------------------------------------
static inline void* symAddr(const void* sym) {
    void* p = nullptr;
    cudaGetSymbolAddress(&p, sym);
    return p;
}

extern "C" void kernel_launch(void* const* d_in, const int* in_sizes, int n_in,
                              void* d_out, int out_size)
{
    const float* x        = (const float*)d_in[0];
    const int*   eidx     = (const int*)  d_in[1];
    const int*   etype    = (const int*)  d_in[2];
    const int*   batch    = (const int*)  d_in[3];
    const float* enc_W    = (const float*)d_in[4];
    const float* enc_b    = (const float*)d_in[5];
    const float* W_skip0  = (const float*)d_in[6];
    const float* F_skip0  = (const float*)d_in[7];
    const float* W_rel0   = (const float*)d_in[8];
    const float* F_rel0   = (const float*)d_in[9];
    const float* W_skip1  = (const float*)d_in[10];
    const float* F_skip1  = (const float*)d_in[11];
    const float* W_rel1   = (const float*)d_in[12];
    const float* F_rel1   = (const float*)d_in[13];
    const float* bn_g     = (const float*)d_in[14];
    const float* bn_b     = (const float*)d_in[15];
    const float* lin_W    = (const float*)d_in[16];
    const float* lin_b    = (const float*)d_in[17];
    const float* clf_W    = (const float*)d_in[18];
    const float* clf_b    = (const float*)d_in[19];
    float* out = (float*)d_out;

    const int* src = eidx;       // edge_index[0]
    const int* dst = eidx + EE;  // edge_index[1]

    float* h0     = (float*)symAddr(g_h0);
    float* h1     = (float*)symAddr(g_h1);
    float* C      = (float*)symAddr(g_C);
    float* Wc0    = (float*)symAddr(g_Wcat);
    float* Wc1    = Wc0 + (size_t)HH * MC;
    float* sums   = (float*)symAddr(g_sums);
    float* pool   = (float*)symAddr(g_pool);
    int*   icnt   = (int*)symAddr(g_icnt);
    int*   off    = (int*)symAddr(g_off);
    int*   cursor = (int*)symAddr(g_cursor);
    int*   bsum   = (int*)symAddr(g_bsum);
    int*   ssrc   = (int*)symAddr(g_ssrc);

    const int NT = 256;
    const int nTilesN = (NN + GT_N - 1) / GT_N;   // 782

    // ---- pack weights for both layers ----
    pack_weights_kernel<<<(HH * MC + NT - 1) / NT, NT>>>(W_skip0, F_skip0, W_rel0, F_rel0, Wc0);
    pack_weights_kernel<<<(HH * MC + NT - 1) / NT, NT>>>(W_skip1, F_skip1, W_rel1, F_rel1, Wc1);

    // ---- CSR build over (r,dst) bins (shared by both layers) ----
    cudaMemsetAsync(icnt,   0, (size_t)RN * sizeof(int));
    cudaMemsetAsync(cursor, 0, (size_t)RN * sizeof(int));
    hist_kernel<<<(EE + NT - 1) / NT, NT>>>(dst, etype, icnt);
    scan1_kernel<<<SCAN_NB, SCAN_BS>>>(icnt, off, bsum, RN);
    scan2_kernel<<<1, SCAN_BS>>>(bsum, SCAN_NB);
    scan3b_kernel<<<SCAN_NB, SCAN_BS>>>(off, bsum, RN);
    scatter_kernel<<<(EE + NT - 1) / NT, NT>>>(src, dst, etype, off, cursor, ssrc);

    // ---- encoder: h0 = x @ enc_W + enc_b ----
    gemm_kernel<<<dim3(1, nTilesN), NT>>>(x, enc_W, enc_b, h0, NN, IND, HH);

    const float* hin = h0;
    for (int layer = 0; layer < 2; layer++) {
        const float* Wc = layer ? Wc1 : Wc0;

        // fused dense phase: C[N, 960] = hin @ Wcat
        gemm_kernel<<<dim3(MC / GT_M, nTilesN), NT>>>(hin, Wc, nullptr, C, NN, HH, MC);

        // edge phase: CSR gather, no atomics, writes means (incl. zeros)
        gather_kernel<<<(RN * 16 + NT - 1) / NT, NT>>>(ssrc, off, icnt, C, sums);

        // finalize
        if (layer == 0) {
            finalize_kernel<<<(unsigned)(((long)NN * 16 + NT - 1) / NT), NT>>>(
                C, sums, bn_g, bn_b, h1, nullptr, nullptr, 0);
            hin = h1;
        } else {
            cudaMemsetAsync(pool, 0, (size_t)GG * HH * sizeof(float));
            finalize_kernel<<<(unsigned)(((long)NN * 16 + NT - 1) / NT), NT>>>(
                C, sums, nullptr, nullptr, nullptr, batch, pool, 1);
        }
    }

    // ---- head ----
    head_kernel<<<1, 128>>>(pool, lin_W, lin_b, clf_W, clf_b, out);
}